// round 11
// baseline (speedup 1.0000x reference)
#include <cuda_runtime.h>

#define TPB   256
#define DIM   4096
#define KSEL  409
#define NWARP (TPB / 32)
#define MAXC  512
#define CAND  1024

// 256 exact power-of-two bins over (1.5, 2.0]: bin = (|x|-1.5)*512 via
// fma(|x|,512,-768), EXACT for |x| in (1.5,2) -> deterministic membership.
// >=2.0 saturates into overflow bin 255; top-down cumulative == count(|x| >= edge).
// Pass 1 additionally appends every |x|>1.5 element (~547/row) to a compact
// candidate list so the rank-bin gather scans ~547 values instead of 4096.
// Correctness layering: list complete -> gather from list; list overflow
// (+20 sigma) -> gather from staged row; rank bin not found -> exact bisection.
__global__ __launch_bounds__(TPB, 8) void sparsify_kernel(const float* __restrict__ x,
                                                          float* __restrict__ out) {
    __shared__ float    s_row[DIM];            // 16 KB staged row
    __shared__ float    s_cand[CAND];          // 4 KB candidate values (|x|>1.5)
    __shared__ int      s_hist[256];
    __shared__ unsigned s_w[NWARP];
    __shared__ float    s_wf[NWARP];
    __shared__ float    s_memb[MAXC];
    __shared__ int      s_cna;                 // candidate count
    __shared__ int      s_cnt;                 // rank-bin member count
    __shared__ int      s_selbin, s_need;
    __shared__ float    s_thr;

    const int t    = threadIdx.x;
    const int lane = t & 31;
    const int wid  = t >> 5;

    const float4* xr    = reinterpret_cast<const float4*>(x + (size_t)blockIdx.x * DIM);
    float4*       orow  = reinterpret_cast<float4*>(out + (size_t)blockIdx.x * DIM);
    float4*       srow4 = reinterpret_cast<float4*>(s_row);

    s_hist[t] = 0;
    if (t == 0) { s_cna = 0; s_cnt = 0; s_selbin = 255; s_need = 1; s_thr = 1.645f; }
    __syncthreads();                                   // B1

    // ---- pass 1: stream load -> stage to smem -> histogram + candidate list ----
    #pragma unroll
    for (int u = 0; u < 4; u++) {
        float4 v = __ldcs(&xr[t + u * TPB]);
        srow4[t + u * TPB] = v;
        #define HC(e) { float av = fabsf(e); \
                        float d = fmaf(av, 512.0f, -768.0f); \
                        if (d > 0.0f) { \
                            int b = min(__float2int_rz(d), 255); \
                            atomicAdd(&s_hist[b], 1); \
                            int id = atomicAdd(&s_cna, 1); \
                            if (id < CAND) s_cand[id] = av; } }
        HC(v.x) HC(v.y) HC(v.z) HC(v.w)
        #undef HC
    }
    __syncthreads();                                   // B2

    // ---- warp 0: top-down scan of 256 bins -> rank bin + local rank ----
    if (wid == 0) {
        const int base = 255 - 8 * lane;               // lane0: bins 255..248, ...
        int h[8]; int lsum = 0;
        #pragma unroll
        for (int k = 0; k < 8; k++) { h[k] = s_hist[base - k]; lsum += h[k]; }
        int cum = lsum;
        #pragma unroll
        for (int o = 1; o < 32; o <<= 1) {
            int n = __shfl_up_sync(0xFFFFFFFFu, cum, o);
            if (lane >= o) cum += n;
        }
        unsigned bal = __ballot_sync(0xFFFFFFFFu, cum >= KSEL);
        if (bal) {
            int L = __ffs(bal) - 1;
            if (lane == L) {
                int ca = cum - lsum;                   // count strictly above lane's bins
                int sel = 255, r = 1;
                #pragma unroll
                for (int k = 0; k < 8; k++) {
                    if (ca + h[k] >= KSEL) { sel = base - k; r = KSEL - ca; break; }
                    ca += h[k];
                }
                s_selbin = sel; s_need = r;
            }
        }
        // bal == 0 -> s_selbin stays 255 -> fallback
    }
    __syncthreads();                                   // B3

    const int sb = s_selbin;                           // uniform across CTA
    const int c0 = s_cna;
    int nd;
    if (sb < 255 && c0 <= CAND) {
        // ---- fast gather: scan candidate list (~547 entries) for rank bin ----
        nd = s_need;
        for (int j = t; j < c0; j += TPB) {
            float av = s_cand[j];                      // av > 1.5 by construction
            float d  = fmaf(av, 512.0f, -768.0f);
            if (__float2int_rz(d) == sb) {             // sb<255: no clamp needed
                int id = atomicAdd(&s_cnt, 1);
                if (id < MAXC) s_memb[id] = av;
            }
        }
    } else if (sb < 255) {
        // ---- rare: list overflowed; gather rank bin from staged row ----
        nd = s_need;
        #pragma unroll
        for (int u = 0; u < 4; u++) {
            float4 v = srow4[t + u * TPB];
            #define TG(e) { float d = fmaf(fabsf(e), 512.0f, -768.0f); \
                            if (d > 0.0f && __float2int_rz(d) == sb) { \
                                int id = atomicAdd(&s_cnt, 1); \
                                if (id < MAXC) s_memb[id] = fabsf(e); } }
            TG(v.x) TG(v.y) TG(v.z) TG(v.w)
            #undef TG
        }
    } else {
        // ---- generic fallback: exact bisection over smem row (~never taken) ----
        float m = 0.0f;
        #pragma unroll
        for (int u = 0; u < 4; u++) {
            float4 v = srow4[t + u * TPB];
            m = fmaxf(m, fmaxf(fmaxf(fabsf(v.x), fabsf(v.y)),
                               fmaxf(fabsf(v.z), fabsf(v.w))));
        }
        #pragma unroll
        for (int o = 16; o; o >>= 1) m = fmaxf(m, __shfl_xor_sync(0xFFFFFFFFu, m, o));
        if (lane == 0) s_wf[wid] = m;
        __syncthreads();
        float maxv = s_wf[0];
        #pragma unroll
        for (int w = 1; w < NWARP; w++) maxv = fmaxf(maxv, s_wf[w]);
        __syncthreads();

        float lo = -1.0f, hi = maxv;
        int cLo = DIM, cHi = 0, guard = 0;
        while ((cLo - cHi) > (MAXC - 64) && guard < 40) {
            float mid = 0.5f * (lo + hi);
            if (!(mid > lo && mid < hi)) break;        // degenerate (ties)
            int cc = 0;
            #pragma unroll
            for (int u = 0; u < 4; u++) {
                float4 v = srow4[t + u * TPB];
                cc += fabsf(v.x) > mid; cc += fabsf(v.y) > mid;
                cc += fabsf(v.z) > mid; cc += fabsf(v.w) > mid;
            }
            unsigned r = __reduce_add_sync(0xFFFFFFFFu, (unsigned)cc);
            if (lane == 0) s_w[wid] = r;
            __syncthreads();
            unsigned tot = 0;
            #pragma unroll
            for (int w = 0; w < NWARP; w++) tot += s_w[w];
            __syncthreads();
            if ((int)tot >= KSEL) { lo = mid; cLo = (int)tot; }
            else                  { hi = mid; cHi = (int)tot; }
            guard++;
        }
        if (t == 0) s_cnt = 0;
        __syncthreads();
        #pragma unroll
        for (int u = 0; u < 4; u++) {
            float4 v = srow4[t + u * TPB];
            #define TG2(e) { float av = fabsf(e); \
                             if (av > lo && av <= hi) { int id = atomicAdd(&s_cnt, 1); \
                                 if (id < MAXC) s_memb[id] = av; } }
            TG2(v.x) TG2(v.y) TG2(v.z) TG2(v.w)
            #undef TG2
        }
        nd = KSEL - cHi;
    }
    __syncthreads();                                   // B4

    // ---- exact select: nd-th largest among c members (typically c ~ 2-4) ----
    const int c = min(s_cnt, MAXC);
    for (int j = t; j < c; j += TPB) {
        float vj = s_memb[j];
        int gt = 0, ge = 0;
        for (int i = 0; i < c; i++) {
            float vi = s_memb[i];
            gt += vi > vj;
            ge += vi >= vj;
        }
        if (gt < nd && nd <= ge) s_thr = vj;           // matching writers write same value
    }
    __syncthreads();                                   // B5

    const float thr   = s_thr;
    const float bias5 = -5.0f * thr;

    // ---- fused epilogue: out = x * (0.5 + 0.5*tanh(5*(|x|-thr))), streaming store ----
    #pragma unroll
    for (int u = 0; u < 4; u++) {
        float4 v = srow4[t + u * TPB];
        float4 o;
        #define MK(dst, xv) { float z = fmaf(5.0f, fabsf(xv), bias5); float th; \
                              asm("tanh.approx.f32 %0, %1;" : "=f"(th) : "f"(z)); \
                              dst = (xv) * fmaf(0.5f, th, 0.5f); }
        MK(o.x, v.x) MK(o.y, v.y) MK(o.z, v.z) MK(o.w, v.w)
        #undef MK
        __stcs(&orow[t + u * TPB], o);
    }
}

extern "C" void kernel_launch(void* const* d_in, const int* in_sizes, int n_in,
                              void* d_out, int out_size) {
    const float* x = (const float*)d_in[0];
    float* out = (float*)d_out;
    const int rows = in_sizes[0] / DIM;   // 4 * 2048 = 8192 rows
    sparsify_kernel<<<rows, TPB>>>(x, out);
}